// round 12
// baseline (speedup 1.0000x reference)
#include <cuda_runtime.h>

#define HH 512
#define WW 512
#define NB 8
#define HID 64
#define TH 0.012271846303085129f   // 2*pi/512
#define INV_N2 3.814697265625e-06f // 1/(512*512)
#define RT2H 0.7071067811865476f   // sqrt(2)/2

typedef unsigned long long u64;

// ---------------- scratch (static device globals; no allocation) -------------
__device__ float  g_R2[16 * NB * HH];     // [v][b*512+h], v = 2*ky + (0:re / 1:im)
__device__ float2 g_Z[NB * HID * 8 * 8];  // [b][j][ky][kx]
__device__ float  g_alpha[HID];
__device__ float  g_beta[HID];

// ---------------- f32x2 packed helpers ---------------------------------------
__device__ __forceinline__ u64 pk2(float lo, float hi) {
    u64 r; asm("mov.b64 %0, {%1,%2};" : "=l"(r) : "f"(lo), "f"(hi)); return r;
}
__device__ __forceinline__ void upk2(u64 v, float& lo, float& hi) {
    asm("mov.b64 {%0,%1}, %2;" : "=f"(lo), "=f"(hi) : "l"(v));
}
__device__ __forceinline__ u64 fma2(u64 a, u64 b, u64 c) {
    u64 d; asm("fma.rn.f32x2 %0, %1, %2, %3;" : "=l"(d) : "l"(a), "l"(b), "l"(c)); return d;
}
__device__ __forceinline__ u64 mul2(u64 a, u64 b) {
    u64 d; asm("mul.rn.f32x2 %0, %1, %2;" : "=l"(d) : "l"(a), "l"(b)); return d;
}
__device__ __forceinline__ u64 add2(u64 a, u64 b) {
    u64 d; asm("add.rn.f32x2 %0, %1, %2;" : "=l"(d) : "l"(a), "l"(b)); return d;
}

// ============ stage 1: per-row partial DFT via per-thread FFT-8, 2 rows/block =
__global__ void __launch_bounds__(128) k_rowdft(const float* __restrict__ x) {
    const int b = blockIdx.y;
    const int tid = threadIdx.x;
    const int g = tid >> 6, lt = tid & 63;
    const int h = blockIdx.x * 2 + g;

    __shared__ float sv[128 * 17];
    __shared__ float sp[2][4 * 17];

    const float* row = x + ((size_t)b * HH + h) * WW;
    float x0 = row[lt], x1 = row[lt + 64], x2 = row[lt + 128], x3 = row[lt + 192];
    float x4 = row[lt + 256], x5 = row[lt + 320], x6 = row[lt + 384], x7 = row[lt + 448];

    // 8-point real DFT
    float a0 = x0 + x4, a1 = x1 + x5, a2 = x2 + x6, a3 = x3 + x7;
    float bb0 = x0 - x4, bb1 = x1 - x5, bb2 = x2 - x6, bb3 = x3 - x7;
    float c0 = a0 + a2, c1 = a0 - a2, c2 = a1 + a3, c3 = a1 - a3;
    float p = RT2H * (bb1 - bb3);
    float q = RT2H * (bb1 + bb3);

    float Xr[8], Xi[8];
    Xr[0] = c0 + c2;   Xi[0] = 0.f;
    Xr[4] = c0 - c2;   Xi[4] = 0.f;
    Xr[2] = c1;        Xi[2] = -c3;
    Xr[6] = c1;        Xi[6] =  c3;
    Xr[1] = bb0 + p;   Xi[1] = -(bb2 + q);
    Xr[7] = bb0 + p;   Xi[7] =  (bb2 + q);
    Xr[3] = bb0 - p;   Xi[3] =  (bb2 - q);
    Xr[5] = bb0 - p;   Xi[5] = -(bb2 - q);

    // V_k = e^{-i k w th} * X8_k, w = lt
    float vals[16];
    {
        float s1v, c1v;
        __sincosf((float)lt * TH, &s1v, &c1v);
        float ck = 1.f, sk = 0.f;
#pragma unroll
        for (int k = 0; k < 8; k++) {
            vals[2 * k]     = ck * Xr[k] + sk * Xi[k];
            vals[2 * k + 1] = ck * Xi[k] - sk * Xr[k];
            float cn = ck * c1v - sk * s1v;
            float sn = sk * c1v + ck * s1v;
            ck = cn; sk = sn;
        }
    }

#pragma unroll
    for (int i = 0; i < 16; i++) sv[tid * 17 + i] = vals[i];
    __syncthreads();

    {
        int v = lt & 15, grp = lt >> 4;   // 4 groups of 16 within this row-group
        float pp = 0.f;
#pragma unroll
        for (int i = 0; i < 16; i++) pp += sv[(g * 64 + grp * 16 + i) * 17 + v];
        sp[g][grp * 17 + v] = pp;
    }
    __syncthreads();

    if (lt < 16) {
        float s = sp[g][lt] + sp[g][17 + lt] + sp[g][34 + lt] + sp[g][51 + lt];
        g_R2[lt * (NB * HH) + b * HH + h] = s;
    }
}

// ============ stage 2: fused column-DFT + mode chain + affine =================
__global__ void __launch_bounds__(128) k_spectral(const float* __restrict__ spec_wr,
                                                  const float* __restrict__ spec_wi,
                                                  const float* __restrict__ conv_w,
                                                  const float* __restrict__ conv_b,
                                                  const float* __restrict__ fc0_w,
                                                  const float* __restrict__ fc0_b,
                                                  const float* __restrict__ fc1_w,
                                                  const float* __restrict__ fc1_b) {
    const int site = blockIdx.x;
    const int kx = site >> 3, ky = site & 7;
    const bool dc = (site == 0);
    const int t = threadIdx.x;
    const int b = t >> 4, o = t & 15;

    __shared__ float swr[768];
    __shared__ float swi[768];
    __shared__ float scw[768];
    __shared__ float sfc1[1024];
    __shared__ float sXr[NB], sXi[NB];
    __shared__ float2 X[NB][16], Y0[NB][16], Y1[NB][16], Y2[NB][16];

    float rwr[6], rwi[6], rcw[6], rf1[8];
#pragma unroll
    for (int q = 0; q < 6; q++) {
        int i = t + 128 * q;
        rwr[q] = spec_wr[(size_t)i * 64 + site];
        rwi[q] = spec_wi[(size_t)i * 64 + site];
        rcw[q] = conv_w[i];
    }
#pragma unroll
    for (int q = 0; q < 8; q++) rf1[q] = fc1_w[t + 128 * q];

    if (t < NB) { sXr[t] = 0.f; sXi[t] = 0.f; }
    __syncthreads();

    {
        const int chunk = t & 15;
        const float* pr = g_R2 + (2 * ky) * (NB * HH) + b * HH;
        const float* pim = g_R2 + (2 * ky + 1) * (NB * HH) + b * HH;
        float c0, s0, cs, ss;
        __sincosf((float)kx * TH * (float)chunk, &s0, &c0);
        __sincosf((float)kx * TH * 16.f, &ss, &cs);
        float ck = c0, sk = s0;
        float vr = 0.f, vi = 0.f;
#pragma unroll 4
        for (int it = 0; it < 32; it++) {
            int hh = chunk + 16 * it;
            float rr = pr[hh], ri = pim[hh];
            vr += rr * ck + ri * sk;
            vi += ri * ck - rr * sk;
            float cn = ck * cs - sk * ss;
            float sn = sk * cs + ck * ss;
            ck = cn; sk = sn;
        }
        atomicAdd(&sXr[b], vr);
        atomicAdd(&sXi[b], vi);
    }

#pragma unroll
    for (int q = 0; q < 6; q++) {
        int i = t + 128 * q;
        swr[i] = rwr[q];
        swi[i] = rwi[q];
        scw[i] = rcw[q];
    }
#pragma unroll
    for (int q = 0; q < 8; q++) sfc1[t + 128 * q] = rf1[q];
    __syncthreads();

    if (dc && t < 32) {
        int oo = t & 15;
        float v = fc0_w[oo], bbv = fc0_b[oo];
        for (int d = 0; d < 3; d++) {
            float sv_ = 0.f, sb_ = 0.f;
#pragma unroll
            for (int c = 0; c < 16; c++) {
                float vv = __shfl_sync(0xffffffffu, v, c);
                float bv = __shfl_sync(0xffffffffu, bbv, c);
                float cw = scw[d * 256 + oo * 16 + c];
                sv_ += cw * vv;
                sb_ += cw * bv;
            }
            v = sv_;
            bbv = sb_ + conv_b[d * 16 + oo];
        }
        for (int jj = t; jj < 64; jj += 32) {
            float a = 0.f, be = 0.f;
#pragma unroll
            for (int o2 = 0; o2 < 16; o2++) {
                float vv = __shfl_sync(0xffffffffu, v, o2);
                float bv = __shfl_sync(0xffffffffu, bbv, o2);
                float f = sfc1[o2 * 64 + jj];
                a  += f * vv;
                be += f * bv;
            }
            g_alpha[jj] = a;
            g_beta[jj]  = be + fc1_b[jj];
        }
    }

    {
        float xr = sXr[b] * INV_N2;
        float xi = sXi[b] * INV_N2;
        float w0 = fc0_w[o];
        X[b][o] = make_float2(w0 * xr + (dc ? fc0_b[o] : 0.f), w0 * xi);
    }
    __syncthreads();

    for (int d = 0; d < 3; d++) {
        float yr = 0.f, yi = 0.f;
#pragma unroll
        for (int c = 0; c < 16; c++) {
            float wr = swr[(d * 16 + c) * 16 + o], wim = swi[(d * 16 + c) * 16 + o];
            float xr = X[b][c].x, xi = X[b][c].y;
            yr += xr * wr - xi * wim;
            yi += xr * wim + xi * wr;
        }
        if (d == 0) Y0[b][o] = make_float2(yr, yi);
        else if (d == 1) Y1[b][o] = make_float2(yr, yi);
        else Y2[b][o] = make_float2(yr, yi);

        float gyr = yr, gyi = yi;
        if (ky == 0) {
            if (kx == 0) gyi = 0.f;
            else { gyr *= 0.5f; gyi *= 0.5f; }
        }
        float nr = gyr, ni = gyi;
#pragma unroll
        for (int c = 0; c < 16; c++) {
            float cw = scw[d * 256 + o * 16 + c];
            nr += cw * X[b][c].x;
            ni += cw * X[b][c].y;
        }
        if (dc) nr += conv_b[d * 16 + o];
        __syncthreads();
        X[b][o] = make_float2(nr, ni);
        __syncthreads();
    }

    {
        float tr = Y1[b][o].x, ti = Y1[b][o].y;
#pragma unroll
        for (int c = 0; c < 16; c++) {
            float cw = scw[1 * 256 + o * 16 + c];
            tr += cw * Y0[b][c].x;
            ti += cw * Y0[b][c].y;
        }
        __syncthreads();
        X[b][o] = make_float2(tr, ti);
        __syncthreads();
        float yr = Y2[b][o].x, yi = Y2[b][o].y;
#pragma unroll
        for (int c = 0; c < 16; c++) {
            float cw = scw[2 * 256 + o * 16 + c];
            yr += cw * X[b][c].x;
            yi += cw * X[b][c].y;
        }
        __syncthreads();
        Y0[b][o] = make_float2(yr, yi);
        __syncthreads();
    }

#pragma unroll
    for (int r = 0; r < 4; r++) {
        int j = (t & 15) + 16 * r;
        float zr = 0.f, zi = 0.f;
#pragma unroll
        for (int o2 = 0; o2 < 16; o2++) {
            float f = sfc1[o2 * 64 + j];
            zr += f * Y0[b][o2].x;
            zi += f * Y0[b][o2].y;
        }
        g_Z[(((size_t)b * HID + j) * 8 + ky) * 8 + kx] = make_float2(zr, zi);
    }
}

// ============ stage 3: per-pixel eval (round-8 shape: 64 thr x 8 px, hoisted) =
__global__ void __launch_bounds__(64) k_main(const float* __restrict__ x,
                                             const float* __restrict__ fc2_w,
                                             const float* __restrict__ fc2_b,
                                             float* __restrict__ out) {
    const int b = blockIdx.y, h = blockIdx.x;
    const int tid = threadIdx.x;

    __shared__ __align__(16) float tabf[32][16][2];
    __shared__ __align__(8)  float fc2f[32][2];

    // row phases e^{+i kx th_h}
    float pc[8], ps[8];
    {
        float s1, c1;
        __sincosf((float)h * TH, &s1, &c1);
        float ck = 1.f, sk = 0.f;
#pragma unroll
        for (int k = 0; k < 8; k++) {
            pc[k] = ck; ps[k] = sk;
            float cn = ck * c1 - sk * s1;
            float sn = sk * c1 + ck * s1;
            ck = cn; sk = sn;
        }
    }

#pragma unroll
    for (int r = 0; r < 8; r++) {
        int idx = tid + 64 * r;   // j*8 + ky
        int j = idx >> 3, ky = idx & 7;
        const float4* zp = (const float4*)(g_Z + (((size_t)b * HID + j) * 8 + ky) * 8);
        float4 z01 = zp[0], z23 = zp[1], z45 = zp[2], z67 = zp[3];
        float ar, ai;
        ar  = z01.x * pc[0] - z01.y * ps[0];  ai  = z01.x * ps[0] + z01.y * pc[0];
        ar += z01.z * pc[1] - z01.w * ps[1];  ai += z01.z * ps[1] + z01.w * pc[1];
        ar += z23.x * pc[2] - z23.y * ps[2];  ai += z23.x * ps[2] + z23.y * pc[2];
        ar += z23.z * pc[3] - z23.w * ps[3];  ai += z23.z * ps[3] + z23.w * pc[3];
        ar += z45.x * pc[4] - z45.y * ps[4];  ai += z45.x * ps[4] + z45.y * pc[4];
        ar += z45.z * pc[5] - z45.w * ps[5];  ai += z45.z * ps[5] + z45.w * pc[5];
        ar += z67.x * pc[6] - z67.y * ps[6];  ai += z67.x * ps[6] + z67.y * pc[6];
        ar += z67.z * pc[7] - z67.w * ps[7];  ai += z67.z * ps[7] + z67.w * pc[7];

        int jp = j & 31, ln = j >> 5;
        if (ky == 0) {
            tabf[jp][14][ln] = g_alpha[j];
            tabf[jp][15][ln] = g_beta[j] + ar;   // c0 = Re(A)
            fc2f[jp][ln]     = fc2_w[j];
        } else {
            int slot = (ky & 1) ? (5 + ky) : (ky - 2);
            tabf[jp][slot][ln]     = 2.f * ar;
            tabf[jp][slot + 1][ln] = -2.f * ai;
        }
    }

    // basis for base pixels wA=tid, wB=tid+64 (broadcast to both lanes)
    float b0[16], b1[16];
    {
        float s1, c1;
        __sincosf((float)tid * TH, &s1, &c1);
        float ck = 1.f, sk = 0.f;
#pragma unroll
        for (int k = 0; k < 8; k++) {
            b0[2 * k] = ck; b0[2 * k + 1] = sk;
            float cn = ck * c1 - sk * s1;
            float sn = sk * c1 + ck * s1;
            ck = cn; sk = sn;
        }
    }
    {
        float s1, c1;
        __sincosf((float)(tid + 64) * TH, &s1, &c1);
        float ck = 1.f, sk = 0.f;
#pragma unroll
        for (int k = 0; k < 8; k++) {
            b1[2 * k] = ck; b1[2 * k + 1] = sk;
            float cn = ck * c1 - sk * s1;
            float sn = sk * c1 + ck * s1;
            ck = cn; sk = sn;
        }
    }
    u64 AE0 = pk2(b0[4],  b0[4]),  AE1 = pk2(b0[5],  b0[5]);
    u64 AE2 = pk2(b0[8],  b0[8]),  AE3 = pk2(b0[9],  b0[9]);
    u64 AE4 = pk2(b0[12], b0[12]), AE5 = pk2(b0[13], b0[13]);
    u64 AO0 = pk2(b0[2],  b0[2]),  AO1 = pk2(b0[3],  b0[3]);
    u64 AO2 = pk2(b0[6],  b0[6]),  AO3 = pk2(b0[7],  b0[7]);
    u64 AO4 = pk2(b0[10], b0[10]), AO5 = pk2(b0[11], b0[11]);
    u64 AO6 = pk2(b0[14], b0[14]), AO7 = pk2(b0[15], b0[15]);
    u64 BE0 = pk2(b1[4],  b1[4]),  BE1 = pk2(b1[5],  b1[5]);
    u64 BE2 = pk2(b1[8],  b1[8]),  BE3 = pk2(b1[9],  b1[9]);
    u64 BE4 = pk2(b1[12], b1[12]), BE5 = pk2(b1[13], b1[13]);
    u64 BO0 = pk2(b1[2],  b1[2]),  BO1 = pk2(b1[3],  b1[3]);
    u64 BO2 = pk2(b1[6],  b1[6]),  BO3 = pk2(b1[7],  b1[7]);
    u64 BO4 = pk2(b1[10], b1[10]), BO5 = pk2(b1[11], b1[11]);
    u64 BO6 = pk2(b1[14], b1[14]), BO7 = pk2(b1[15], b1[15]);

    const float* xrow = x + ((size_t)b * HH + h) * WW;
    u64 xb[8];
#pragma unroll
    for (int m = 0; m < 8; m++) {
        float xv = xrow[tid + 64 * m];
        xb[m] = pk2(xv, xv);
    }
    const u64 NEG1 = pk2(-1.f, -1.f);

    __syncthreads();

    u64 acc[8];
#pragma unroll
    for (int m = 0; m < 8; m++) acc[m] = pk2(0.f, 0.f);

#pragma unroll 1
    for (int jp = 0; jp < 32; jp++) {
        const ulonglong2* tj = (const ulonglong2*)(&tabf[jp][0][0]);
        ulonglong2 q0 = tj[0], q1 = tj[1], q2 = tj[2], q3 = tj[3];
        ulonglong2 q4 = tj[4], q5 = tj[5], q6 = tj[6], q7 = tj[7];
        u64 w2p = *(const u64*)(&fc2f[jp][0]);

        // ---- family A: pixels m=0 (w), m=4 (+256), m=2 (+128), m=6 (+384) ----
        u64 ePA = fma2(q1.y, AE3, mul2(q1.x, AE2));
        u64 eMA = fma2(q2.y, AE5, fma2(q2.x, AE4,
                  fma2(q0.y, AE1, mul2(q0.x, AE0))));
        u64 oA  = fma2(q6.y, AO7, fma2(q6.x, AO6, fma2(q5.y, AO5,
                  fma2(q5.x, AO4, fma2(q4.y, AO3, fma2(q4.x, AO2,
                  fma2(q3.y, AO1, mul2(q3.x, AO0))))))));
        u64 oPA = fma2(q6.x, AO7, fma2(q5.y, AO4,
                  fma2(q4.x, AO3, mul2(q3.y, AO0))));
        u64 oMA = fma2(q6.y, AO6, fma2(q5.x, AO5,
                  fma2(q4.y, AO2, mul2(q3.x, AO1))));
        u64 eA  = add2(ePA, eMA);
        u64 eA2 = fma2(eMA, NEG1, ePA);
        u64 dA  = fma2(oMA, NEG1, oPA);

        u64 s0_ = add2(q7.y, eA);
        u64 BA0 = add2(s0_, oA);
        u64 BA2 = fma2(oA, NEG1, s0_);
        u64 s1_ = add2(q7.y, eA2);
        u64 BA1 = add2(s1_, dA);
        u64 BA3 = fma2(dA, NEG1, s1_);

        {
            u64 u_ = fma2(q7.x, xb[0], BA0);
            float lo, hi; upk2(u_, lo, hi);
            acc[0] = fma2(w2p, pk2(fmaxf(lo, 0.f), fmaxf(hi, 0.f)), acc[0]);
        }
        {
            u64 u_ = fma2(q7.x, xb[2], BA1);
            float lo, hi; upk2(u_, lo, hi);
            acc[2] = fma2(w2p, pk2(fmaxf(lo, 0.f), fmaxf(hi, 0.f)), acc[2]);
        }
        {
            u64 u_ = fma2(q7.x, xb[4], BA2);
            float lo, hi; upk2(u_, lo, hi);
            acc[4] = fma2(w2p, pk2(fmaxf(lo, 0.f), fmaxf(hi, 0.f)), acc[4]);
        }
        {
            u64 u_ = fma2(q7.x, xb[6], BA3);
            float lo, hi; upk2(u_, lo, hi);
            acc[6] = fma2(w2p, pk2(fmaxf(lo, 0.f), fmaxf(hi, 0.f)), acc[6]);
        }

        // ---- family B: pixels m=1 (w+64), m=3, m=5, m=7 ----
        u64 ePB = fma2(q1.y, BE3, mul2(q1.x, BE2));
        u64 eMB = fma2(q2.y, BE5, fma2(q2.x, BE4,
                  fma2(q0.y, BE1, mul2(q0.x, BE0))));
        u64 oB  = fma2(q6.y, BO7, fma2(q6.x, BO6, fma2(q5.y, BO5,
                  fma2(q5.x, BO4, fma2(q4.y, BO3, fma2(q4.x, BO2,
                  fma2(q3.y, BO1, mul2(q3.x, BO0))))))));
        u64 oPB = fma2(q6.x, BO7, fma2(q5.y, BO4,
                  fma2(q4.x, BO3, mul2(q3.y, BO0))));
        u64 oMB = fma2(q6.y, BO6, fma2(q5.x, BO5,
                  fma2(q4.y, BO2, mul2(q3.x, BO1))));
        u64 eB  = add2(ePB, eMB);
        u64 eB2 = fma2(eMB, NEG1, ePB);
        u64 dB  = fma2(oMB, NEG1, oPB);

        u64 s2_ = add2(q7.y, eB);
        u64 BB0 = add2(s2_, oB);
        u64 BB2 = fma2(oB, NEG1, s2_);
        u64 s3_ = add2(q7.y, eB2);
        u64 BB1 = add2(s3_, dB);
        u64 BB3 = fma2(dB, NEG1, s3_);

        {
            u64 u_ = fma2(q7.x, xb[1], BB0);
            float lo, hi; upk2(u_, lo, hi);
            acc[1] = fma2(w2p, pk2(fmaxf(lo, 0.f), fmaxf(hi, 0.f)), acc[1]);
        }
        {
            u64 u_ = fma2(q7.x, xb[3], BB1);
            float lo, hi; upk2(u_, lo, hi);
            acc[3] = fma2(w2p, pk2(fmaxf(lo, 0.f), fmaxf(hi, 0.f)), acc[3]);
        }
        {
            u64 u_ = fma2(q7.x, xb[5], BB2);
            float lo, hi; upk2(u_, lo, hi);
            acc[5] = fma2(w2p, pk2(fmaxf(lo, 0.f), fmaxf(hi, 0.f)), acc[5]);
        }
        {
            u64 u_ = fma2(q7.x, xb[7], BB3);
            float lo, hi; upk2(u_, lo, hi);
            acc[7] = fma2(w2p, pk2(fmaxf(lo, 0.f), fmaxf(hi, 0.f)), acc[7]);
        }
    }

    float ob = fc2_b[0];
    float* orow = out + ((size_t)b * HH + h) * WW;
#pragma unroll
    for (int m = 0; m < 8; m++) {
        float lo, hi;
        upk2(acc[m], lo, hi);
        orow[tid + 64 * m] = lo + hi + ob;
    }
}

// ---------------- launch -----------------------------------------------------
extern "C" void kernel_launch(void* const* d_in, const int* in_sizes, int n_in,
                              void* d_out, int out_size) {
    const float* x       = (const float*)d_in[0];
    const float* fc0_w   = (const float*)d_in[1];
    const float* fc0_b   = (const float*)d_in[2];
    const float* spec_wr = (const float*)d_in[3];
    const float* spec_wi = (const float*)d_in[4];
    const float* conv_w  = (const float*)d_in[5];
    const float* conv_b  = (const float*)d_in[6];
    const float* fc1_w   = (const float*)d_in[7];
    const float* fc1_b   = (const float*)d_in[8];
    const float* fc2_w   = (const float*)d_in[9];
    const float* fc2_b   = (const float*)d_in[10];
    float* out = (float*)d_out;

    k_rowdft<<<dim3(HH / 2, NB), 128>>>(x);
    k_spectral<<<64, 128>>>(spec_wr, spec_wi, conv_w, conv_b,
                            fc0_w, fc0_b, fc1_w, fc1_b);
    k_main<<<dim3(HH, NB), 64>>>(x, fc2_w, fc2_b, out);
}

// round 13
// speedup vs baseline: 1.0611x; 1.0611x over previous
#include <cuda_runtime.h>

#define HH 512
#define WW 512
#define NB 8
#define HID 64
#define TH 0.012271846303085129f   // 2*pi/512
#define INV_N2 3.814697265625e-06f // 1/(512*512)
#define RT2H 0.7071067811865476f   // sqrt(2)/2

typedef unsigned long long u64;

// ---------------- scratch (static device globals; no allocation) -------------
__device__ float  g_R2[16 * NB * HH];     // [v][b*512+h], v = 2*ky + (0:re / 1:im)
__device__ float2 g_Z[NB * HID * 8 * 8];  // [b][j][ky][kx]
__device__ float  g_alpha[HID];
__device__ float  g_beta[HID];

// ---------------- f32x2 packed helpers ---------------------------------------
__device__ __forceinline__ u64 pk2(float lo, float hi) {
    u64 r; asm("mov.b64 %0, {%1,%2};" : "=l"(r) : "f"(lo), "f"(hi)); return r;
}
__device__ __forceinline__ void upk2(u64 v, float& lo, float& hi) {
    asm("mov.b64 {%0,%1}, %2;" : "=f"(lo), "=f"(hi) : "l"(v));
}
__device__ __forceinline__ u64 fma2(u64 a, u64 b, u64 c) {
    u64 d; asm("fma.rn.f32x2 %0, %1, %2, %3;" : "=l"(d) : "l"(a), "l"(b), "l"(c)); return d;
}
__device__ __forceinline__ u64 mul2(u64 a, u64 b) {
    u64 d; asm("mul.rn.f32x2 %0, %1, %2;" : "=l"(d) : "l"(a), "l"(b)); return d;
}
__device__ __forceinline__ u64 add2(u64 a, u64 b) {
    u64 d; asm("add.rn.f32x2 %0, %1, %2;" : "=l"(d) : "l"(a), "l"(b)); return d;
}

// ============ stage 1: per-row partial DFT via per-thread FFT-8, 2 rows/block =
__global__ void __launch_bounds__(128) k_rowdft(const float* __restrict__ x) {
    const int b = blockIdx.y;
    const int tid = threadIdx.x;
    const int g = tid >> 6, lt = tid & 63;
    const int h = blockIdx.x * 2 + g;

    __shared__ float sv[128 * 17];
    __shared__ float sp[2][4 * 17];

    const float* row = x + ((size_t)b * HH + h) * WW;
    float x0 = row[lt], x1 = row[lt + 64], x2 = row[lt + 128], x3 = row[lt + 192];
    float x4 = row[lt + 256], x5 = row[lt + 320], x6 = row[lt + 384], x7 = row[lt + 448];

    float a0 = x0 + x4, a1 = x1 + x5, a2 = x2 + x6, a3 = x3 + x7;
    float bb0 = x0 - x4, bb1 = x1 - x5, bb2 = x2 - x6, bb3 = x3 - x7;
    float c0 = a0 + a2, c1 = a0 - a2, c2 = a1 + a3, c3 = a1 - a3;
    float p = RT2H * (bb1 - bb3);
    float q = RT2H * (bb1 + bb3);

    float Xr[8], Xi[8];
    Xr[0] = c0 + c2;   Xi[0] = 0.f;
    Xr[4] = c0 - c2;   Xi[4] = 0.f;
    Xr[2] = c1;        Xi[2] = -c3;
    Xr[6] = c1;        Xi[6] =  c3;
    Xr[1] = bb0 + p;   Xi[1] = -(bb2 + q);
    Xr[7] = bb0 + p;   Xi[7] =  (bb2 + q);
    Xr[3] = bb0 - p;   Xi[3] =  (bb2 - q);
    Xr[5] = bb0 - p;   Xi[5] = -(bb2 - q);

    float vals[16];
    {
        float s1v, c1v;
        __sincosf((float)lt * TH, &s1v, &c1v);
        float ck = 1.f, sk = 0.f;
#pragma unroll
        for (int k = 0; k < 8; k++) {
            vals[2 * k]     = ck * Xr[k] + sk * Xi[k];
            vals[2 * k + 1] = ck * Xi[k] - sk * Xr[k];
            float cn = ck * c1v - sk * s1v;
            float sn = sk * c1v + ck * s1v;
            ck = cn; sk = sn;
        }
    }

#pragma unroll
    for (int i = 0; i < 16; i++) sv[tid * 17 + i] = vals[i];
    __syncthreads();

    {
        int v = lt & 15, grp = lt >> 4;
        float pp = 0.f;
#pragma unroll
        for (int i = 0; i < 16; i++) pp += sv[(g * 64 + grp * 16 + i) * 17 + v];
        sp[g][grp * 17 + v] = pp;
    }
    __syncthreads();

    if (lt < 16) {
        float s = sp[g][lt] + sp[g][17 + lt] + sp[g][34 + lt] + sp[g][51 + lt];
        g_R2[lt * (NB * HH) + b * HH + h] = s;
    }
}

// ============ stage 2: fused column-DFT + mode chain + affine =================
__global__ void __launch_bounds__(128) k_spectral(const float* __restrict__ spec_wr,
                                                  const float* __restrict__ spec_wi,
                                                  const float* __restrict__ conv_w,
                                                  const float* __restrict__ conv_b,
                                                  const float* __restrict__ fc0_w,
                                                  const float* __restrict__ fc0_b,
                                                  const float* __restrict__ fc1_w,
                                                  const float* __restrict__ fc1_b) {
    const int site = blockIdx.x;
    const int kx = site >> 3, ky = site & 7;
    const bool dc = (site == 0);
    const int t = threadIdx.x;
    const int b = t >> 4, o = t & 15;

    __shared__ float swr[768];
    __shared__ float swi[768];
    __shared__ float scw[768];
    __shared__ float sfc1[1024];
    __shared__ float sXr[NB], sXi[NB];
    __shared__ float2 X[NB][16], Y0[NB][16], Y1[NB][16], Y2[NB][16];

    float rwr[6], rwi[6], rcw[6], rf1[8];
#pragma unroll
    for (int q = 0; q < 6; q++) {
        int i = t + 128 * q;
        rwr[q] = spec_wr[(size_t)i * 64 + site];
        rwi[q] = spec_wi[(size_t)i * 64 + site];
        rcw[q] = conv_w[i];
    }
#pragma unroll
    for (int q = 0; q < 8; q++) rf1[q] = fc1_w[t + 128 * q];

    if (t < NB) { sXr[t] = 0.f; sXi[t] = 0.f; }
    __syncthreads();

    {
        const int chunk = t & 15;
        const float* pr = g_R2 + (2 * ky) * (NB * HH) + b * HH;
        const float* pim = g_R2 + (2 * ky + 1) * (NB * HH) + b * HH;
        float c0, s0, cs, ss;
        __sincosf((float)kx * TH * (float)chunk, &s0, &c0);
        __sincosf((float)kx * TH * 16.f, &ss, &cs);
        float ck = c0, sk = s0;
        float vr = 0.f, vi = 0.f;
#pragma unroll 4
        for (int it = 0; it < 32; it++) {
            int hh = chunk + 16 * it;
            float rr = pr[hh], ri = pim[hh];
            vr += rr * ck + ri * sk;
            vi += ri * ck - rr * sk;
            float cn = ck * cs - sk * ss;
            float sn = sk * cs + ck * ss;
            ck = cn; sk = sn;
        }
        atomicAdd(&sXr[b], vr);
        atomicAdd(&sXi[b], vi);
    }

#pragma unroll
    for (int q = 0; q < 6; q++) {
        int i = t + 128 * q;
        swr[i] = rwr[q];
        swi[i] = rwi[q];
        scw[i] = rcw[q];
    }
#pragma unroll
    for (int q = 0; q < 8; q++) sfc1[t + 128 * q] = rf1[q];
    __syncthreads();

    if (dc && t < 32) {
        int oo = t & 15;
        float v = fc0_w[oo], bbv = fc0_b[oo];
        for (int d = 0; d < 3; d++) {
            float sv_ = 0.f, sb_ = 0.f;
#pragma unroll
            for (int c = 0; c < 16; c++) {
                float vv = __shfl_sync(0xffffffffu, v, c);
                float bv = __shfl_sync(0xffffffffu, bbv, c);
                float cw = scw[d * 256 + oo * 16 + c];
                sv_ += cw * vv;
                sb_ += cw * bv;
            }
            v = sv_;
            bbv = sb_ + conv_b[d * 16 + oo];
        }
        for (int jj = t; jj < 64; jj += 32) {
            float a = 0.f, be = 0.f;
#pragma unroll
            for (int o2 = 0; o2 < 16; o2++) {
                float vv = __shfl_sync(0xffffffffu, v, o2);
                float bv = __shfl_sync(0xffffffffu, bbv, o2);
                float f = sfc1[o2 * 64 + jj];
                a  += f * vv;
                be += f * bv;
            }
            g_alpha[jj] = a;
            g_beta[jj]  = be + fc1_b[jj];
        }
    }

    {
        float xr = sXr[b] * INV_N2;
        float xi = sXi[b] * INV_N2;
        float w0 = fc0_w[o];
        X[b][o] = make_float2(w0 * xr + (dc ? fc0_b[o] : 0.f), w0 * xi);
    }
    __syncthreads();

    for (int d = 0; d < 3; d++) {
        float yr = 0.f, yi = 0.f;
#pragma unroll
        for (int c = 0; c < 16; c++) {
            float wr = swr[(d * 16 + c) * 16 + o], wim = swi[(d * 16 + c) * 16 + o];
            float xr = X[b][c].x, xi = X[b][c].y;
            yr += xr * wr - xi * wim;
            yi += xr * wim + xi * wr;
        }
        if (d == 0) Y0[b][o] = make_float2(yr, yi);
        else if (d == 1) Y1[b][o] = make_float2(yr, yi);
        else Y2[b][o] = make_float2(yr, yi);

        float gyr = yr, gyi = yi;
        if (ky == 0) {
            if (kx == 0) gyi = 0.f;
            else { gyr *= 0.5f; gyi *= 0.5f; }
        }
        float nr = gyr, ni = gyi;
#pragma unroll
        for (int c = 0; c < 16; c++) {
            float cw = scw[d * 256 + o * 16 + c];
            nr += cw * X[b][c].x;
            ni += cw * X[b][c].y;
        }
        if (dc) nr += conv_b[d * 16 + o];
        __syncthreads();
        X[b][o] = make_float2(nr, ni);
        __syncthreads();
    }

    {
        float tr = Y1[b][o].x, ti = Y1[b][o].y;
#pragma unroll
        for (int c = 0; c < 16; c++) {
            float cw = scw[1 * 256 + o * 16 + c];
            tr += cw * Y0[b][c].x;
            ti += cw * Y0[b][c].y;
        }
        __syncthreads();
        X[b][o] = make_float2(tr, ti);
        __syncthreads();
        float yr = Y2[b][o].x, yi = Y2[b][o].y;
#pragma unroll
        for (int c = 0; c < 16; c++) {
            float cw = scw[2 * 256 + o * 16 + c];
            yr += cw * X[b][c].x;
            yi += cw * X[b][c].y;
        }
        __syncthreads();
        Y0[b][o] = make_float2(yr, yi);
        __syncthreads();
    }

#pragma unroll
    for (int r = 0; r < 4; r++) {
        int j = (t & 15) + 16 * r;
        float zr = 0.f, zi = 0.f;
#pragma unroll
        for (int o2 = 0; o2 < 16; o2++) {
            float f = sfc1[o2 * 64 + j];
            zr += f * Y0[b][o2].x;
            zi += f * Y0[b][o2].y;
        }
        g_Z[(((size_t)b * HID + j) * 8 + ky) * 8 + kx] = make_float2(zr, zi);
    }
}

// ============ stage 3: per-pixel eval; 64 thr x 8 px, partial hoist ===========
__global__ void __launch_bounds__(64) k_main(const float* __restrict__ x,
                                             const float* __restrict__ fc2_w,
                                             const float* __restrict__ fc2_b,
                                             float* __restrict__ out) {
    const int b = blockIdx.y, h = blockIdx.x;
    const int tid = threadIdx.x;

    __shared__ __align__(16) float tabf[32][16][2];
    __shared__ __align__(8)  float fc2f[32][2];

    // row phases e^{+i kx th_h}
    float pc[8], ps[8];
    {
        float s1, c1;
        __sincosf((float)h * TH, &s1, &c1);
        float ck = 1.f, sk = 0.f;
#pragma unroll
        for (int k = 0; k < 8; k++) {
            pc[k] = ck; ps[k] = sk;
            float cn = ck * c1 - sk * s1;
            float sn = sk * c1 + ck * s1;
            ck = cn; sk = sn;
        }
    }

#pragma unroll
    for (int r = 0; r < 8; r++) {
        int idx = tid + 64 * r;   // j*8 + ky
        int j = idx >> 3, ky = idx & 7;
        const float4* zp = (const float4*)(g_Z + (((size_t)b * HID + j) * 8 + ky) * 8);
        float4 z01 = zp[0], z23 = zp[1], z45 = zp[2], z67 = zp[3];
        float ar, ai;
        ar  = z01.x * pc[0] - z01.y * ps[0];  ai  = z01.x * ps[0] + z01.y * pc[0];
        ar += z01.z * pc[1] - z01.w * ps[1];  ai += z01.z * ps[1] + z01.w * pc[1];
        ar += z23.x * pc[2] - z23.y * ps[2];  ai += z23.x * ps[2] + z23.y * pc[2];
        ar += z23.z * pc[3] - z23.w * ps[3];  ai += z23.z * ps[3] + z23.w * pc[3];
        ar += z45.x * pc[4] - z45.y * ps[4];  ai += z45.x * ps[4] + z45.y * pc[4];
        ar += z45.z * pc[5] - z45.w * ps[5];  ai += z45.z * ps[5] + z45.w * pc[5];
        ar += z67.x * pc[6] - z67.y * ps[6];  ai += z67.x * ps[6] + z67.y * pc[6];
        ar += z67.z * pc[7] - z67.w * ps[7];  ai += z67.z * ps[7] + z67.w * pc[7];

        int jp = j & 31, ln = j >> 5;
        if (ky == 0) {
            tabf[jp][14][ln] = g_alpha[j];
            tabf[jp][15][ln] = g_beta[j] + ar;   // c0 = Re(A)
            fc2f[jp][ln]     = fc2_w[j];
        } else {
            int slot = (ky & 1) ? (5 + ky) : (ky - 2);
            tabf[jp][slot][ln]     = 2.f * ar;
            tabf[jp][slot + 1][ln] = -2.f * ai;
        }
    }

    // basis for base pixel wA = tid; wB = tid+64 via exact k*pi/4 rotation
    float b0[16], b1[16];
    {
        float s1, c1;
        __sincosf((float)tid * TH, &s1, &c1);
        float ck = 1.f, sk = 0.f;
#pragma unroll
        for (int k = 0; k < 8; k++) {
            b0[2 * k] = ck; b0[2 * k + 1] = sk;
            float cn = ck * c1 - sk * s1;
            float sn = sk * c1 + ck * s1;
            ck = cn; sk = sn;
        }
    }
    {
        // rotate by k*pi/4: cos/sin in {0, ±1, ±RT2H}
        b1[0]  = 1.f;                              b1[1]  = 0.f;
        b1[2]  = (b0[2] - b0[3]) * RT2H;           b1[3]  = (b0[3] + b0[2]) * RT2H;
        b1[4]  = -b0[5];                           b1[5]  =  b0[4];
        b1[6]  = -(b0[6] + b0[7]) * RT2H;          b1[7]  = (b0[6] - b0[7]) * RT2H;
        b1[8]  = -b0[8];                           b1[9]  = -b0[9];
        b1[10] = (b0[11] - b0[10]) * RT2H;         b1[11] = -(b0[10] + b0[11]) * RT2H;
        b1[12] =  b0[13];                          b1[13] = -b0[12];
        b1[14] = (b0[14] + b0[15]) * RT2H;         b1[15] = (b0[15] - b0[14]) * RT2H;
    }
    u64 AE0 = pk2(b0[4],  b0[4]),  AE1 = pk2(b0[5],  b0[5]);
    u64 AE2 = pk2(b0[8],  b0[8]),  AE3 = pk2(b0[9],  b0[9]);
    u64 AE4 = pk2(b0[12], b0[12]), AE5 = pk2(b0[13], b0[13]);
    u64 AO0 = pk2(b0[2],  b0[2]),  AO1 = pk2(b0[3],  b0[3]);
    u64 AO2 = pk2(b0[6],  b0[6]),  AO3 = pk2(b0[7],  b0[7]);
    u64 AO4 = pk2(b0[10], b0[10]), AO5 = pk2(b0[11], b0[11]);
    u64 AO6 = pk2(b0[14], b0[14]), AO7 = pk2(b0[15], b0[15]);
    u64 BE0 = pk2(b1[4],  b1[4]),  BE1 = pk2(b1[5],  b1[5]);
    u64 BE2 = pk2(b1[8],  b1[8]),  BE3 = pk2(b1[9],  b1[9]);
    u64 BE4 = pk2(b1[12], b1[12]), BE5 = pk2(b1[13], b1[13]);
    u64 BO0 = pk2(b1[2],  b1[2]),  BO1 = pk2(b1[3],  b1[3]);
    u64 BO2 = pk2(b1[6],  b1[6]),  BO3 = pk2(b1[7],  b1[7]);
    u64 BO4 = pk2(b1[10], b1[10]), BO5 = pk2(b1[11], b1[11]);
    u64 BO6 = pk2(b1[14], b1[14]), BO7 = pk2(b1[15], b1[15]);

    const float* xrow = x + ((size_t)b * HH + h) * WW;
    u64 xb[8];
#pragma unroll
    for (int m = 0; m < 8; m++) {
        float xv = xrow[tid + 64 * m];
        xb[m] = pk2(xv, xv);
    }
    const u64 NEG1 = pk2(-1.f, -1.f);

    __syncthreads();

    u64 acc[8];
#pragma unroll
    for (int m = 0; m < 8; m++) acc[m] = pk2(0.f, 0.f);

#pragma unroll 1
    for (int jp = 0; jp < 32; jp++) {
        const ulonglong2* tj = (const ulonglong2*)(&tabf[jp][0][0]);
        ulonglong2 q0 = tj[0], q1 = tj[1], q2 = tj[2], q3 = tj[3];
        ulonglong2 q4 = tj[4], q5 = tj[5], q6 = tj[6], q7 = tj[7];
        u64 w2p = *(const u64*)(&fc2f[jp][0]);

        // ---- family A: pixels m=0, m=4(+256), m=2(+128), m=6(+384) ----
        u64 ePA = fma2(q1.y, AE3, mul2(q1.x, AE2));
        u64 eMA = fma2(q2.y, AE5, fma2(q2.x, AE4,
                  fma2(q0.y, AE1, mul2(q0.x, AE0))));
        u64 oA  = fma2(q6.y, AO7, fma2(q6.x, AO6, fma2(q5.y, AO5,
                  fma2(q5.x, AO4, fma2(q4.y, AO3, fma2(q4.x, AO2,
                  fma2(q3.y, AO1, mul2(q3.x, AO0))))))));
        u64 oPA = fma2(q6.x, AO7, fma2(q5.y, AO4,
                  fma2(q4.x, AO3, mul2(q3.y, AO0))));
        u64 oMA = fma2(q6.y, AO6, fma2(q5.x, AO5,
                  fma2(q4.y, AO2, mul2(q3.x, AO1))));
        u64 dA  = fma2(oMA, NEG1, oPA);
        u64 sA0 = add2(q7.y, add2(ePA, eMA));
        u64 sA1 = add2(q7.y, fma2(eMA, NEG1, ePA));

        {
            u64 u_ = add2(fma2(q7.x, xb[0], sA0), oA);
            float lo, hi; upk2(u_, lo, hi);
            acc[0] = fma2(w2p, pk2(fmaxf(lo, 0.f), fmaxf(hi, 0.f)), acc[0]);
        }
        {
            u64 u_ = fma2(oA, NEG1, fma2(q7.x, xb[4], sA0));
            float lo, hi; upk2(u_, lo, hi);
            acc[4] = fma2(w2p, pk2(fmaxf(lo, 0.f), fmaxf(hi, 0.f)), acc[4]);
        }
        {
            u64 u_ = add2(fma2(q7.x, xb[2], sA1), dA);
            float lo, hi; upk2(u_, lo, hi);
            acc[2] = fma2(w2p, pk2(fmaxf(lo, 0.f), fmaxf(hi, 0.f)), acc[2]);
        }
        {
            u64 u_ = fma2(dA, NEG1, fma2(q7.x, xb[6], sA1));
            float lo, hi; upk2(u_, lo, hi);
            acc[6] = fma2(w2p, pk2(fmaxf(lo, 0.f), fmaxf(hi, 0.f)), acc[6]);
        }

        // ---- family B: pixels m=1(+64), m=5, m=3, m=7 ----
        u64 ePB = fma2(q1.y, BE3, mul2(q1.x, BE2));
        u64 eMB = fma2(q2.y, BE5, fma2(q2.x, BE4,
                  fma2(q0.y, BE1, mul2(q0.x, BE0))));
        u64 oB  = fma2(q6.y, BO7, fma2(q6.x, BO6, fma2(q5.y, BO5,
                  fma2(q5.x, BO4, fma2(q4.y, BO3, fma2(q4.x, BO2,
                  fma2(q3.y, BO1, mul2(q3.x, BO0))))))));
        u64 oPB = fma2(q6.x, BO7, fma2(q5.y, BO4,
                  fma2(q4.x, BO3, mul2(q3.y, BO0))));
        u64 oMB = fma2(q6.y, BO6, fma2(q5.x, BO5,
                  fma2(q4.y, BO2, mul2(q3.x, BO1))));
        u64 dB  = fma2(oMB, NEG1, oPB);
        u64 sB0 = add2(q7.y, add2(ePB, eMB));
        u64 sB1 = add2(q7.y, fma2(eMB, NEG1, ePB));

        {
            u64 u_ = add2(fma2(q7.x, xb[1], sB0), oB);
            float lo, hi; upk2(u_, lo, hi);
            acc[1] = fma2(w2p, pk2(fmaxf(lo, 0.f), fmaxf(hi, 0.f)), acc[1]);
        }
        {
            u64 u_ = fma2(oB, NEG1, fma2(q7.x, xb[5], sB0));
            float lo, hi; upk2(u_, lo, hi);
            acc[5] = fma2(w2p, pk2(fmaxf(lo, 0.f), fmaxf(hi, 0.f)), acc[5]);
        }
        {
            u64 u_ = add2(fma2(q7.x, xb[3], sB1), dB);
            float lo, hi; upk2(u_, lo, hi);
            acc[3] = fma2(w2p, pk2(fmaxf(lo, 0.f), fmaxf(hi, 0.f)), acc[3]);
        }
        {
            u64 u_ = fma2(dB, NEG1, fma2(q7.x, xb[7], sB1));
            float lo, hi; upk2(u_, lo, hi);
            acc[7] = fma2(w2p, pk2(fmaxf(lo, 0.f), fmaxf(hi, 0.f)), acc[7]);
        }
    }

    float ob = fc2_b[0];
    float* orow = out + ((size_t)b * HH + h) * WW;
#pragma unroll
    for (int m = 0; m < 8; m++) {
        float lo, hi;
        upk2(acc[m], lo, hi);
        orow[tid + 64 * m] = lo + hi + ob;
    }
}

// ---------------- launch -----------------------------------------------------
extern "C" void kernel_launch(void* const* d_in, const int* in_sizes, int n_in,
                              void* d_out, int out_size) {
    const float* x       = (const float*)d_in[0];
    const float* fc0_w   = (const float*)d_in[1];
    const float* fc0_b   = (const float*)d_in[2];
    const float* spec_wr = (const float*)d_in[3];
    const float* spec_wi = (const float*)d_in[4];
    const float* conv_w  = (const float*)d_in[5];
    const float* conv_b  = (const float*)d_in[6];
    const float* fc1_w   = (const float*)d_in[7];
    const float* fc1_b   = (const float*)d_in[8];
    const float* fc2_w   = (const float*)d_in[9];
    const float* fc2_b   = (const float*)d_in[10];
    float* out = (float*)d_out;

    k_rowdft<<<dim3(HH / 2, NB), 128>>>(x);
    k_spectral<<<64, 128>>>(spec_wr, spec_wi, conv_w, conv_b,
                            fc0_w, fc0_b, fc1_w, fc1_b);
    k_main<<<dim3(HH, NB), 64>>>(x, fc2_w, fc2_b, out);
}